// round 4
// baseline (speedup 1.0000x reference)
#include <cuda_runtime.h>
#include <cuda_bf16.h>
#include <math.h>

// Problem constants
#define NT   8192      // tokens
#define DH   2048      // hidden
#define KW   9         // conv kernel width
#define PAD  4         // KW/2
#define DIN1 600       // input feature dim

// -------- scratch (static device globals; no allocation) --------
__device__ float g_wt1[(size_t)KW * DIN1 * DH];   //  44 MB: W1 transposed to [(k*DIN+c), n]
__device__ float g_wt2[(size_t)KW * DH   * DH];   // 151 MB: W2 transposed
__device__ float g_h1 [(size_t)NT * DH];          //  67 MB: layer-1 activations
__device__ float g_h2 [(size_t)NT * DH];          //  67 MB: layer-2 activations
__device__ int   g_seg[NT];                       // canonical int32 segment keys

// ============================================================================
// Segment-key normalization. The reference casts to int64 but JAX's default
// (x64 disabled) silently produces int32 — so the true dtype is ambiguous.
// Detect at runtime: keys are sorted values in [0,64). If the buffer is int64
// (little-endian), every odd int32 word is a zero hi-word. If int32, the
// sorted tail (word 8191) is ~63 != 0. Sample several odd words to decide.
// ============================================================================
__global__ void normalize_seg_kernel(const int* __restrict__ seg32)
{
    // cheap redundant detection per thread (3 loads, L2-hit after first block)
    bool is64 = (seg32[8191] == 0) && (seg32[4097] == 0) && (seg32[6143] == 0);
    int i = blockIdx.x * blockDim.x + threadIdx.x;
    if (i < NT)
        g_seg[i] = is64 ? seg32[2 * i] : seg32[i];
}

// ============================================================================
// Weight transpose: w [DH, DIN, KW] (n,c,k) -> wt [(k*DIN + c), DH] (kk, n)
// ============================================================================
__global__ void transpose_w_kernel(const float* __restrict__ w, int din, int which, size_t total)
{
    size_t idx = (size_t)blockIdx.x * blockDim.x + threadIdx.x;
    if (idx >= total) return;
    int    k = (int)(idx % KW);
    size_t t = idx / KW;
    int    c = (int)(t % din);
    int    n = (int)(t / din);
    float* wt = (which == 1) ? g_wt1 : g_wt2;
    wt[((size_t)k * din + c) * DH + n] = w[idx];
}

// ============================================================================
// Segment-masked conv layer as a tiled GEMM with fused bias+ReLU+BatchNorm.
//   Y[i,n] = BN(ReLU( b[n] + sum_k sum_c mask(i,k) * X[i+k-4, c] * W[n,c,k] ))
// BM=128, BN=128, BK=8, 256 threads, 8x8 register tile per thread.
// ============================================================================
template<int DIN, int LAYER>
__global__ __launch_bounds__(256, 2)
void conv_gemm_kernel(const float* __restrict__ Xin,
                      const float* __restrict__ bias,
                      const float* __restrict__ gam,
                      const float* __restrict__ bet,
                      const float* __restrict__ mu,
                      const float* __restrict__ var)
{
    constexpr int BM = 128, BN = 128, BK = 8;

    __shared__ float As[BK][BM + 4];     // +4 pad -> conflict-free transposed stores
    __shared__ float Bs[BK][BN];
    __shared__ float msk[BM][KW + 1];    // per (row, k) segment mask as 0/1 float

    const float* X  = (LAYER == 1) ? Xin : g_h1;
    const float* Wt = (LAYER == 1) ? g_wt1 : g_wt2;
    float*       Y  = (LAYER == 1) ? g_h1 : g_h2;

    const int tid  = threadIdx.x;
    const int row0 = blockIdx.x * BM;
    const int col0 = blockIdx.y * BN;

    // --- precompute segment masks for this row tile ---
    for (int t = tid; t < BM * KW; t += 256) {
        int r = t / KW;
        int k = t - r * KW;
        int src = row0 + r + k - PAD;
        float mm = 0.0f;
        if (src >= 0 && src < NT && g_seg[src] == g_seg[row0 + r]) mm = 1.0f;
        msk[r][k] = mm;
    }
    __syncthreads();

    float acc[8][8];
#pragma unroll
    for (int i = 0; i < 8; ++i)
#pragma unroll
        for (int j = 0; j < 8; ++j) acc[i][j] = 0.0f;

    // load-index mapping
    const int a_row = tid >> 1;            // 0..127
    const int a_kk  = (tid & 1) << 2;      // 0 or 4
    const int b_kk  = tid >> 5;            // 0..7
    const int b_n   = (tid & 31) << 2;     // 0..124
    // compute-index mapping (16x16 threads, 8x8 each)
    const int tr = (tid >> 4) << 3;
    const int tc = (tid & 15) << 3;

#pragma unroll 1
    for (int k = 0; k < KW; ++k) {
        int srow = row0 + a_row + k - PAD;
        srow = srow < 0 ? 0 : (srow >= NT ? NT - 1 : srow);   // clamp; mask kills OOB
        const float  mm   = msk[a_row][k];
        const float* xrow = X + (size_t)srow * DIN;
        const float* wcol = Wt + (size_t)k * DIN * DH + (size_t)b_kk * DH + col0 + b_n;

#pragma unroll 1
        for (int c0 = 0; c0 < DIN; c0 += BK) {
            // issue global loads before the barrier (overlap with prior compute drain)
            float4 av = *reinterpret_cast<const float4*>(xrow + c0 + a_kk);
            float4 bv = *reinterpret_cast<const float4*>(wcol + (size_t)c0 * DH);
            __syncthreads();
            As[a_kk + 0][a_row] = av.x * mm;
            As[a_kk + 1][a_row] = av.y * mm;
            As[a_kk + 2][a_row] = av.z * mm;
            As[a_kk + 3][a_row] = av.w * mm;
            *reinterpret_cast<float4*>(&Bs[b_kk][b_n]) = bv;
            __syncthreads();

#pragma unroll
            for (int kk = 0; kk < BK; ++kk) {
                float ra[8], rb[8];
                *(float4*)(ra)     = *(const float4*)(&As[kk][tr]);
                *(float4*)(ra + 4) = *(const float4*)(&As[kk][tr + 4]);
                *(float4*)(rb)     = *(const float4*)(&Bs[kk][tc]);
                *(float4*)(rb + 4) = *(const float4*)(&Bs[kk][tc + 4]);
#pragma unroll
                for (int i = 0; i < 8; ++i)
#pragma unroll
                    for (int j = 0; j < 8; ++j)
                        acc[i][j] = fmaf(ra[i], rb[j], acc[i][j]);
            }
        }
    }

    // --- fused epilogue: y = relu(acc + b) * scale + shift ---
    float sc[8], sh[8], bb[8];
#pragma unroll
    for (int j = 0; j < 8; ++j) {
        int n  = col0 + tc + j;
        float s = gam[n] * rsqrtf(var[n] + 1e-5f);
        sc[j] = s;
        sh[j] = bet[n] - mu[n] * s;
        bb[j] = bias[n];
    }
#pragma unroll
    for (int i = 0; i < 8; ++i) {
        float yv[8];
#pragma unroll
        for (int j = 0; j < 8; ++j)
            yv[j] = fmaxf(acc[i][j] + bb[j], 0.0f) * sc[j] + sh[j];
        float* yp = Y + (size_t)(row0 + tr + i) * DH + col0 + tc;
        *(float4*)(yp)     = *(float4*)(yv);
        *(float4*)(yp + 4) = *(float4*)(yv + 4);
    }
}

// ============================================================================
// Head: logits = h2 @ w_lin^T + b_lin ; probs = softmax(logits, axis=1)
// One warp per row. out[0:2N] = logits, out[2N:4N] = probs.
// ============================================================================
__global__ void head_kernel(const float* __restrict__ wlin,
                            const float* __restrict__ blin,
                            float* __restrict__ out, int out_elems)
{
    int gtid = blockIdx.x * blockDim.x + threadIdx.x;
    int row  = gtid >> 5;
    int lane = gtid & 31;
    if (row >= NT) return;

    const float* hr = g_h2 + (size_t)row * DH;
    float s0 = 0.0f, s1 = 0.0f;
    for (int j = lane; j < DH; j += 32) {
        float x = hr[j];
        s0 = fmaf(x, wlin[j],      s0);
        s1 = fmaf(x, wlin[DH + j], s1);
    }
#pragma unroll
    for (int o = 16; o > 0; o >>= 1) {
        s0 += __shfl_down_sync(0xFFFFFFFFu, s0, o);
        s1 += __shfl_down_sync(0xFFFFFFFFu, s1, o);
    }
    if (lane == 0) {
        float o0 = s0 + blin[0];
        float o1 = s1 + blin[1];
        out[2 * row]     = o0;
        out[2 * row + 1] = o1;
        if (out_elems >= 4 * NT) {
            float mx = fmaxf(o0, o1);
            float e0 = expf(o0 - mx);
            float e1 = expf(o1 - mx);
            float inv = 1.0f / (e0 + e1);
            out[2 * NT + 2 * row]     = e0 * inv;
            out[2 * NT + 2 * row + 1] = e1 * inv;
        }
    }
}

// ============================================================================
extern "C" void kernel_launch(void* const* d_in, const int* in_sizes, int n_in,
                              void* d_out, int out_size)
{
    const float* latent = (const float*) d_in[0];
    const int*   seg    = (const int*)   d_in[1];   // dtype auto-detected on device
    const float* w1     = (const float*) d_in[2];
    const float* b1     = (const float*) d_in[3];
    const float* g1     = (const float*) d_in[4];
    const float* be1    = (const float*) d_in[5];
    const float* m1     = (const float*) d_in[6];
    const float* v1     = (const float*) d_in[7];
    const float* w2     = (const float*) d_in[8];
    const float* b2     = (const float*) d_in[9];
    const float* g2     = (const float*) d_in[10];
    const float* be2    = (const float*) d_in[11];
    const float* m2     = (const float*) d_in[12];
    const float* v2     = (const float*) d_in[13];
    const float* wlin   = (const float*) d_in[14];
    const float* blin   = (const float*) d_in[15];
    float*       out    = (float*)       d_out;

    // 0) canonicalize segment keys (handles int32 or int64 buffers)
    normalize_seg_kernel<<<(NT + 255) / 256, 256>>>(seg);

    // 1) transpose weights into GEMM-friendly layout
    size_t tot1 = (size_t)DH * DIN1 * KW;
    size_t tot2 = (size_t)DH * DH   * KW;
    transpose_w_kernel<<<(unsigned)((tot1 + 255) / 256), 256>>>(w1, DIN1, 1, tot1);
    transpose_w_kernel<<<(unsigned)((tot2 + 255) / 256), 256>>>(w2, DH,   2, tot2);

    // 2) conv layers (fused bias + ReLU + BN)
    dim3 grid(NT / 128, DH / 128);
    conv_gemm_kernel<DIN1, 1><<<grid, 256>>>(latent, b1, g1, be1, m1, v1);
    conv_gemm_kernel<DH,   2><<<grid, 256>>>(nullptr, b2, g2, be2, m2, v2);

    // 3) linear head + softmax
    head_kernel<<<(NT * 32 + 255) / 256, 256>>>(wlin, blin, out, out_size);
}

// round 8
// speedup vs baseline: 1.9145x; 1.9145x over previous
#include <cuda_runtime.h>
#include <cuda_bf16.h>
#include <math.h>
#include <stdint.h>

// ---------------- problem constants ----------------
#define NT    8192
#define DH    2048
#define KW    9
#define PAD   4
#define DIN1  600
#define DINP1 640      // DIN1 padded to multiple of 64
#define DINP2 2048

// ---------------- device-global scratch (no allocation) ----------------
__device__ int            g_seg[NT];
__device__ __nv_bfloat16  g_x1h[(size_t)NT * DINP1];
__device__ __nv_bfloat16  g_x1l[(size_t)NT * DINP1];
__device__ __nv_bfloat16  g_x2h[(size_t)NT * DH];
__device__ __nv_bfloat16  g_x2l[(size_t)NT * DH];
__device__ __nv_bfloat16  g_w1h[(size_t)KW * DH * DINP1];
__device__ __nv_bfloat16  g_w1l[(size_t)KW * DH * DINP1];
__device__ __nv_bfloat16  g_w2h[(size_t)KW * DH * DINP2];
__device__ __nv_bfloat16  g_w2l[(size_t)KW * DH * DINP2];
__device__ float          g_h2[(size_t)NT * DH];

// ---------------- helpers ----------------
__device__ __forceinline__ uint32_t smem_u32(const void* p) {
    uint32_t a;
    asm("{ .reg .u64 t; cvta.to.shared.u64 t, %1; cvt.u32.u64 %0, t; }" : "=r"(a) : "l"(p));
    return a;
}
__device__ __forceinline__ void cp_async16(uint32_t dst, const void* src, uint32_t src_bytes) {
    asm volatile("cp.async.cg.shared.global [%0], [%1], 16, %2;"
                 :: "r"(dst), "l"(src), "r"(src_bytes) : "memory");
}
__device__ __forceinline__ void cp_commit() {
    asm volatile("cp.async.commit_group;" ::: "memory");
}
template<int N>
__device__ __forceinline__ void cp_wait() {
    asm volatile("cp.async.wait_group %0;" :: "n"(N) : "memory");
}
__device__ __forceinline__ void ldmatrix_x4(uint32_t* r, uint32_t addr) {
    asm volatile("ldmatrix.sync.aligned.m8n8.x4.shared.b16 {%0,%1,%2,%3}, [%4];"
                 : "=r"(r[0]), "=r"(r[1]), "=r"(r[2]), "=r"(r[3]) : "r"(addr));
}
__device__ __forceinline__ void ldmatrix_x2(uint32_t* r, uint32_t addr) {
    asm volatile("ldmatrix.sync.aligned.m8n8.x2.shared.b16 {%0,%1}, [%2];"
                 : "=r"(r[0]), "=r"(r[1]) : "r"(addr));
}
__device__ __forceinline__ void mma_bf16(float* c, const uint32_t* a, const uint32_t* b) {
    asm volatile("mma.sync.aligned.m16n8k16.row.col.f32.bf16.bf16.f32 "
                 "{%0,%1,%2,%3}, {%4,%5,%6,%7}, {%8,%9}, {%0,%1,%2,%3};"
                 : "+f"(c[0]), "+f"(c[1]), "+f"(c[2]), "+f"(c[3])
                 : "r"(a[0]), "r"(a[1]), "r"(a[2]), "r"(a[3]), "r"(b[0]), "r"(b[1]));
}

// ============================================================================
// Prep kernels
// ============================================================================
__global__ void normalize_seg_kernel(const int* __restrict__ seg32) {
    bool is64 = (seg32[8191] == 0) && (seg32[4097] == 0) && (seg32[6143] == 0);
    int i = blockIdx.x * blockDim.x + threadIdx.x;
    if (i < NT) g_seg[i] = is64 ? seg32[2 * i] : seg32[i];
}

__global__ void split_x_kernel(const float* __restrict__ x) {
    size_t i = (size_t)blockIdx.x * blockDim.x + threadIdx.x;
    if (i >= (size_t)NT * DINP1) return;
    int c = (int)(i % DINP1);
    int r = (int)(i / DINP1);
    float v = (c < DIN1) ? x[(size_t)r * DIN1 + c] : 0.0f;
    __nv_bfloat16 h = __float2bfloat16(v);
    g_x1h[i] = h;
    g_x1l[i] = __float2bfloat16(v - __bfloat162float(h));
}

// w [DH, din, KW] -> wh/wl [KW][DH][dinp] bf16 (k-contiguous per (tap,n) row)
__global__ void split_w_kernel(const float* __restrict__ w, int din, int dinp, int which, int total) {
    int i = blockIdx.x * blockDim.x + threadIdx.x;   // over DH * dinp
    if (i >= total) return;
    int c = i % dinp;
    int n = i / dinp;
    __nv_bfloat16* oh = (which == 1) ? g_w1h : g_w2h;
    __nv_bfloat16* ol = (which == 1) ? g_w1l : g_w2l;
#pragma unroll
    for (int k = 0; k < KW; ++k) {
        float v = (c < din) ? w[((size_t)n * din + c) * KW + k] : 0.0f;
        __nv_bfloat16 h = __float2bfloat16(v);
        size_t o = ((size_t)k * DH + n) * dinp + c;
        oh[o] = h;
        ol[o] = __float2bfloat16(v - __bfloat162float(h));
    }
}

// ============================================================================
// mma.sync bf16 split-3 conv-GEMM, fused bias+ReLU+BN epilogue.
//   CTA 128x128, 8 warps as 2(M) x 4(N), warp tile 64x32.
//   BK=64, double-buffered cp.async; segment mask via cp.async zero-fill.
// ============================================================================
#define LDROW   144                         // (64+8) bf16 = 144B row pitch
#define STAGEB  (128 * LDROW)               // 18432 B per operand per stage
#define OFF_MSK 0
#define OFF_SC  4608
#define OFF_SH  5120
#define OFF_BB  5632
#define OFF_A   6144
#define OFF_B   (OFF_A + 2 * STAGEB)        // 43008
#define SM_TOTAL (OFF_B + 2 * STAGEB)       // 79872 B

template<int DINP, int LAYER>
__global__ __launch_bounds__(256, 2)
void gemm_mma_kernel(const float* __restrict__ bias, const float* __restrict__ gam,
                     const float* __restrict__ bet,  const float* __restrict__ mu,
                     const float* __restrict__ var)
{
    constexpr int NCH = DINP / 64;
    constexpr int NQ  = 3 * KW * NCH;

    extern __shared__ char smem[];
    const uint32_t sb = smem_u32(smem);
    const int tid  = threadIdx.x;
    const int lane = tid & 31;
    const int wid  = tid >> 5;
    const int row0 = blockIdx.x * 128;
    const int col0 = blockIdx.y * 128;

    float* msk = (float*)(smem + OFF_MSK);
    float* ssc = (float*)(smem + OFF_SC);
    float* ssh = (float*)(smem + OFF_SH);
    float* sbb = (float*)(smem + OFF_BB);

    // segment masks + folded BN params
    for (int t = tid; t < 128 * KW; t += 256) {
        int r = t / KW, k = t - r * KW;
        int src = row0 + r + k - PAD;
        msk[r * KW + k] = (src >= 0 && src < NT && g_seg[src] == g_seg[row0 + r]) ? 1.0f : 0.0f;
    }
    if (tid < 128) {
        int n = col0 + tid;
        float s = gam[n] * rsqrtf(var[n] + 1e-5f);
        ssc[tid] = s;
        ssh[tid] = bet[n] - mu[n] * s;
        sbb[tid] = bias[n];
    }
    __syncthreads();

    const __nv_bfloat16* Ah = (LAYER == 1) ? g_x1h : g_x2h;
    const __nv_bfloat16* Al = (LAYER == 1) ? g_x1l : g_x2l;
    const __nv_bfloat16* Bh = (LAYER == 1) ? g_w1h : g_w2h;
    const __nv_bfloat16* Bl = (LAYER == 1) ? g_w1l : g_w2l;

    // per-thread load mapping: row = tid>>1, 4 x 16B chunks covering 64B half-row
    // 2 threads per row x 64B = full 128B (BK=64 bf16) row.  <-- R7 fix
    const int ldr   = tid >> 1;               // 0..127
    const int ldcb  = (tid & 1) * 64;         // byte offset within 128B of row data
    const int ldce  = (tid & 1) * 32;         // element offset
    const uint32_t dstA = sb + OFF_A + ldr * LDROW + ldcb;
    const uint32_t dstB = sb + OFF_B + ldr * LDROW + ldcb;

    // per-warp compute mapping
    const int wm = (wid >> 2) * 64;
    const int wn = (wid & 3) * 32;
    uint32_t aAddr[4], bAddr[4];
#pragma unroll
    for (int mb = 0; mb < 4; ++mb)
        aAddr[mb] = sb + OFF_A + (wm + mb * 16 + (lane & 15)) * LDROW + ((lane >> 4) & 1) * 16;
#pragma unroll
    for (int nb = 0; nb < 4; ++nb)
        bAddr[nb] = sb + OFF_B + (wn + nb * 8 + (lane & 7)) * LDROW + ((lane >> 3) & 1) * 16;

    float acc[4][4][4];
#pragma unroll
    for (int mb = 0; mb < 4; ++mb)
#pragma unroll
        for (int nb = 0; nb < 4; ++nb)
#pragma unroll
            for (int d = 0; d < 4; ++d) acc[mb][nb][d] = 0.0f;

    // stage loader
    auto load_stage = [&](int q, int buf) {
        int pass = q / (KW * NCH);
        int rem  = q - pass * (KW * NCH);
        int tap  = rem / NCH;
        int c0   = (rem - tap * NCH) * 64;
        const __nv_bfloat16* Ap = (pass == 1) ? Al : Ah;   // hh, lh, hl
        const __nv_bfloat16* Bp = (pass == 2) ? Bl : Bh;

        int srow = row0 + ldr + tap - PAD;
        srow = srow < 0 ? 0 : (srow > NT - 1 ? NT - 1 : srow);
        uint32_t asz = (msk[ldr * KW + tap] != 0.0f) ? 16u : 0u;
        const __nv_bfloat16* sa = Ap + (size_t)srow * DINP + c0 + ldce;
        uint32_t da = dstA + buf * STAGEB;
#pragma unroll
        for (int ch = 0; ch < 4; ++ch)
            cp_async16(da + ch * 16, sa + ch * 8, asz);

        const __nv_bfloat16* sbp = Bp + ((size_t)tap * DH + col0 + ldr) * DINP + c0 + ldce;
        uint32_t db = dstB + buf * STAGEB;
#pragma unroll
        for (int ch = 0; ch < 4; ++ch)
            cp_async16(db + ch * 16, sbp + ch * 8, 16u);
    };

    load_stage(0, 0);
    cp_commit();

#pragma unroll 1
    for (int q = 0; q < NQ; ++q) {
        int buf = q & 1;
        if (q + 1 < NQ) { load_stage(q + 1, buf ^ 1); cp_commit(); cp_wait<1>(); }
        else            { cp_wait<0>(); }
        __syncthreads();

        uint32_t bofs = buf * STAGEB;
#pragma unroll
        for (int ks = 0; ks < 4; ++ks) {
            uint32_t afr[4][4], bfr[4][2];
#pragma unroll
            for (int mb = 0; mb < 4; ++mb) ldmatrix_x4(afr[mb], aAddr[mb] + bofs + ks * 32);
#pragma unroll
            for (int nb = 0; nb < 4; ++nb) ldmatrix_x2(bfr[nb], bAddr[nb] + bofs + ks * 32);
#pragma unroll
            for (int mb = 0; mb < 4; ++mb)
#pragma unroll
                for (int nb = 0; nb < 4; ++nb)
                    mma_bf16(acc[mb][nb], afr[mb], bfr[nb]);
        }
        __syncthreads();
    }

    // -------- epilogue: y = relu(acc+b)*sc+sh; layer1 emits bf16 split pair --------
    const int erow = lane >> 2;           // 0..7
    const int ecol = (lane & 3) * 2;      // 0,2,4,6
#pragma unroll
    for (int mb = 0; mb < 4; ++mb) {
#pragma unroll
        for (int nb = 0; nb < 4; ++nb) {
#pragma unroll
            for (int half = 0; half < 2; ++half) {
                int r  = row0 + wm + mb * 16 + erow + half * 8;
                int cl = wn + nb * 8 + ecol;            // local col in [0,128)
                float y0 = fmaxf(acc[mb][nb][half * 2 + 0] + sbb[cl],     0.0f) * ssc[cl]     + ssh[cl];
                float y1 = fmaxf(acc[mb][nb][half * 2 + 1] + sbb[cl + 1], 0.0f) * ssc[cl + 1] + ssh[cl + 1];
                if (LAYER == 1) {
                    __nv_bfloat16 h0 = __float2bfloat16(y0);
                    __nv_bfloat16 h1 = __float2bfloat16(y1);
                    __nv_bfloat162 hv; hv.x = h0; hv.y = h1;
                    __nv_bfloat162 lv;
                    lv.x = __float2bfloat16(y0 - __bfloat162float(h0));
                    lv.y = __float2bfloat16(y1 - __bfloat162float(h1));
                    *(__nv_bfloat162*)(g_x2h + (size_t)r * DH + col0 + cl) = hv;
                    *(__nv_bfloat162*)(g_x2l + (size_t)r * DH + col0 + cl) = lv;
                } else {
                    float2 v; v.x = y0; v.y = y1;
                    *(float2*)(g_h2 + (size_t)r * DH + col0 + cl) = v;
                }
            }
        }
    }
}

// ============================================================================
// Head: logits = h2 @ w_lin^T + b_lin ; probs = softmax. One warp per row.
// ============================================================================
__global__ void head_kernel(const float* __restrict__ wlin, const float* __restrict__ blin,
                            float* __restrict__ out, int out_elems)
{
    int gtid = blockIdx.x * blockDim.x + threadIdx.x;
    int row = gtid >> 5, lane = gtid & 31;
    if (row >= NT) return;
    const float* hr = g_h2 + (size_t)row * DH;
    float s0 = 0.0f, s1 = 0.0f;
    for (int j = lane; j < DH; j += 32) {
        float x = hr[j];
        s0 = fmaf(x, wlin[j], s0);
        s1 = fmaf(x, wlin[DH + j], s1);
    }
#pragma unroll
    for (int o = 16; o > 0; o >>= 1) {
        s0 += __shfl_down_sync(0xFFFFFFFFu, s0, o);
        s1 += __shfl_down_sync(0xFFFFFFFFu, s1, o);
    }
    if (lane == 0) {
        float o0 = s0 + blin[0], o1 = s1 + blin[1];
        out[2 * row] = o0;
        out[2 * row + 1] = o1;
        if (out_elems >= 4 * NT) {
            float mx = fmaxf(o0, o1);
            float e0 = expf(o0 - mx), e1 = expf(o1 - mx);
            float inv = 1.0f / (e0 + e1);
            out[2 * NT + 2 * row]     = e0 * inv;
            out[2 * NT + 2 * row + 1] = e1 * inv;
        }
    }
}

// ============================================================================
extern "C" void kernel_launch(void* const* d_in, const int* in_sizes, int n_in,
                              void* d_out, int out_size)
{
    const float* latent = (const float*) d_in[0];
    const int*   seg    = (const int*)   d_in[1];
    const float* w1     = (const float*) d_in[2];
    const float* b1     = (const float*) d_in[3];
    const float* g1     = (const float*) d_in[4];
    const float* be1    = (const float*) d_in[5];
    const float* m1     = (const float*) d_in[6];
    const float* v1     = (const float*) d_in[7];
    const float* w2     = (const float*) d_in[8];
    const float* b2     = (const float*) d_in[9];
    const float* g2     = (const float*) d_in[10];
    const float* be2    = (const float*) d_in[11];
    const float* m2     = (const float*) d_in[12];
    const float* v2     = (const float*) d_in[13];
    const float* wlin   = (const float*) d_in[14];
    const float* blin   = (const float*) d_in[15];
    float*       out    = (float*)       d_out;

    normalize_seg_kernel<<<(NT + 255) / 256, 256>>>(seg);

    size_t nx = (size_t)NT * DINP1;
    split_x_kernel<<<(unsigned)((nx + 255) / 256), 256>>>(latent);
    int nw1 = DH * DINP1;
    int nw2 = DH * DINP2;
    split_w_kernel<<<(nw1 + 255) / 256, 256>>>(w1, DIN1, DINP1, 1, nw1);
    split_w_kernel<<<(nw2 + 255) / 256, 256>>>(w2, DH,   DINP2, 2, nw2);

    cudaFuncSetAttribute(gemm_mma_kernel<DINP1, 1>,
                         cudaFuncAttributeMaxDynamicSharedMemorySize, SM_TOTAL);
    cudaFuncSetAttribute(gemm_mma_kernel<DINP2, 2>,
                         cudaFuncAttributeMaxDynamicSharedMemorySize, SM_TOTAL);

    dim3 grid(NT / 128, DH / 128);   // x fastest -> CTAs sharing a B panel run together
    gemm_mma_kernel<DINP1, 1><<<grid, 256, SM_TOTAL>>>(b1, g1, be1, m1, v1);
    gemm_mma_kernel<DINP2, 2><<<grid, 256, SM_TOTAL>>>(b2, g2, be2, m2, v2);

    head_kernel<<<(NT * 32 + 255) / 256, 256>>>(wlin, blin, out, out_size);
}